// round 13
// baseline (speedup 1.0000x reference)
#include <cuda_runtime.h>
#include <cuda_fp16.h>
#include <math.h>

// ---------------- constants ----------------
#define NC 80
#define M0 614400
#define M1 153600
#define M2 38400

#define N0 6000
#define N1 4000
#define N2 2000

#define EPSV 1e-7f

#define TPB  256
#define NBLK 592              // one wave; no grid barrier -> no co-residency requirement
#define B1   250              // scale-0 target blocks [0,250)
#define B2   417              // scale-1 [250,417); scale-2 [417,501); dense-only [501,592)
#define TBLK 501
#define WS0  2000             // 250*8 warp slots (x3 lanes = 6000 targets)
#define WS1  1336             // 167*8 (x3 = 4008 >= 4000)
#define WS2  672              // 84*8  (x3 = 2016 >= 2000)
#define MAXK 3                // targets per warp, lanes 0..2 own one each

#define Q0 (M0/4)             // 153600 float4
#define Q1 (M1/4)             // 38400
#define Q2 (M2/4)             // 9600
#define QTOT (Q0+Q1+Q2)       // 201600
#define GSTR (NBLK*TPB)       // 151552 grid stride; GSTR < Q0, 2*GSTR > QTOT

// ---------------- scratch (no allocations allowed) ----------------
// g_tobj holds (tag<<16)|half(v). Stale entries invalidated by tag mismatch ->
// no cleanup pass needed between graph replays.
__device__ unsigned g_tobj[M0 + M1 + M2];   // zero at load (tag 0 never used)
__device__ float    g_pT[NBLK * 3];
__device__ unsigned g_epoch;                // bumped by ticket winner each run
__device__ unsigned g_tk;                   // exit ticket; winner resets

// ---------------- params ----------------
struct P {
    const float* box[3]; const float* cnf[3]; const float* cls[3];
    const float* tbox[3]; const float* anc[3];
    const int* b[3]; const int* a[3]; const int* gy[3]; const int* gx[3]; const int* tc[3];
};

// ---------------- helpers ----------------
__device__ __forceinline__ float sp(float x) {   // softplus = bce(x,0), fast
    return fmaxf(x, 0.f) + __logf(1.f + __expf(-fabsf(x)));
}
__device__ __forceinline__ float sp4(const float4& v) {
    return sp(v.x) + sp(v.y) + sp(v.z) + sp(v.w);
}
__device__ __forceinline__ float sigf(float x) {
    return __fdividef(1.f, 1.f + __expf(-x));
}
__device__ __forceinline__ float comp4(const float4& v, int c) {
    return (c & 2) ? ((c & 1) ? v.w : v.z) : ((c & 1) ? v.y : v.x);
}

__device__ __forceinline__ float ciou(float cx1, float cy1, float w1, float h1,
                                      float cx2, float cy2, float w2, float h2) {
    float x1a = cx1 - w1 * 0.5f, y1a = cy1 - h1 * 0.5f;
    float x2a = cx1 + w1 * 0.5f, y2a = cy1 + h1 * 0.5f;
    float x1b = cx2 - w2 * 0.5f, y1b = cy2 - h2 * 0.5f;
    float x2b = cx2 + w2 * 0.5f, y2b = cy2 + h2 * 0.5f;

    float iw = fmaxf(fminf(x2a, x2b) - fmaxf(x1a, x1b), 0.f);
    float ih = fmaxf(fminf(y2a, y2b) - fmaxf(y1a, y1b), 0.f);
    float inter = iw * ih;
    float uni = (x2a - x1a) * (y2a - y1a) + (x2b - x1b) * (y2b - y1b) - inter;
    float iou = __fdividef(inter, uni + EPSV);

    float cw = fmaxf(x2a, x2b) - fminf(x1a, x1b);
    float ch = fmaxf(y2a, y2b) - fminf(y1a, y1b);
    float diag = cw * cw + ch * ch + EPSV;
    float dx = (x1a + x2a) * 0.5f - (x1b + x2b) * 0.5f;
    float dy = (y1a + y2a) * 0.5f - (y1b + y2b) * 0.5f;
    float cent = dx * dx + dy * dy;

    float at = atanf(__fdividef(x2a - x1a, y2a - y1a + EPSV))
             - atanf(__fdividef(x2b - x1b, y2b - y1b + EPSV));
    const float C4PI2 = 4.0f / (float)(M_PI * M_PI);
    float v = C4PI2 * at * at;
    float alpha = __fdividef(v, v - iou + 1.f + EPSV);
    return iou - (__fdividef(cent, diag) + v * alpha);
}

// release+acquire ticket: orders this thread's prior global stores (release)
// and the winner's subsequent loads (acquire) without a full L1-flushing fence.
__device__ __forceinline__ unsigned ticket_acq_rel(unsigned* addr) {
    unsigned r;
    asm volatile("atom.acq_rel.gpu.global.add.u32 %0, [%1], %2;"
                 : "=r"(r) : "l"(addr), "r"(1u) : "memory");
    return r;
}

// ---------------- per-scale compile-time constants ----------------
template<int SI> struct SC;
template<> struct SC<0> { static constexpr int DIM=80, OFF=0,     NTG=N0, WSL=WS0, BST=0;  static constexpr float W=4.0f/(float)M0; };
template<> struct SC<1> { static constexpr int DIM=40, OFF=M0,    NTG=N1, WSL=WS1, BST=B1; static constexpr float W=1.0f/(float)M1; };
template<> struct SC<2> { static constexpr int DIM=20, OFF=M0+M1, NTG=N2, WSL=WS2, BST=B2; static constexpr float W=0.4f/(float)M2; };

// ---------------- target phase: 3 targets/warp; cls spread over 32 lanes ----
template<int SI>
__device__ __forceinline__ void targets(const P& __restrict__ p, int bx, int tid,
                                        unsigned tag,
                                        float& lb, float& lc, float& lo) {
    const int lane = tid & 31;
    const int wid  = tid >> 5;
    constexpr int DIM = SC<SI>::DIM;
    constexpr float INV_N  = 1.f / (float)SC<SI>::NTG;
    constexpr float INV_NC = 1.f / ((float)SC<SI>::NTG * (float)NC);
    const unsigned FULL = 0xffffffffu;

    const int ws = (bx - SC<SI>::BST) * 8 + wid;

    // --- round 1: lanes 0..2 load their target's index tuple (parallel) ---
    int myBase = -1, myTc = 0, myT = 0;
    if (lane < MAXK) {
        int t = ws + lane * SC<SI>::WSL;
        if (t < SC<SI>::NTG) {
            int bb = p.b[SI][t], aa = p.a[SI][t];
            int yy = p.gy[SI][t], xx = p.gx[SI][t];
            myTc   = p.tc[SI][t];
            myT    = t;
            myBase = ((bb * 3 + aa) * DIM + yy) * DIM + xx;
        }
    }

    // --- cls rows: 3x20 float4 chunks spread flat across 32 lanes ----------
    // slot A: flat f = lane   (0..31):  k = lane>=20 ? 1 : 0
    // slot B: flat f = lane+32 (32..63): k = f<40 ? 1 : 2, valid if f<60
    const int fB = lane + 32;
    const int kA = (lane >= 20) ? 1 : 0;
    const int cA = lane - kA * 20;
    const int kB = (fB < 40) ? 1 : 2;
    const int cB = fB - kB * 20;
    const bool vB = (fB < 60);

    const int baseA = __shfl_sync(FULL, myBase, kA);
    const int tcA   = __shfl_sync(FULL, myTc,  kA);
    const int baseB = __shfl_sync(FULL, myBase, kB);
    const int tcB   = __shfl_sync(FULL, myTc,  kB);

    // --- round 2: all independent gathers issue together ---
    const float4* cls4 = (const float4*)p.cls[SI];
    float4 xA = make_float4(0,0,0,0), xB = xA;
    if (baseA >= 0)       xA = cls4[(size_t)baseA * (NC/4) + cA];
    if (vB && baseB >= 0) xB = cls4[(size_t)baseB * (NC/4) + cB];

    float4 br = make_float4(0,0,0,0), tb = br;
    float2 an = make_float2(0,0);
    float  cn = 0.f;
    if (lane < MAXK && myBase >= 0) {
        br = ((const float4*)p.box[SI])[myBase];
        an = ((const float2*)p.anc[SI])[myT];
        tb = ((const float4*)p.tbox[SI])[myT];
        cn = p.cnf[SI][myBase];
    }

    // --- cls: per-thread accumulation, <=2 chunks per lane, no warp reduce --
    if (baseA >= 0) {
        lc += sp4(xA) * INV_NC;
        if (cA == (tcA >> 2)) lc -= comp4(xA, tcA & 3) * INV_NC;
    }
    if (vB && baseB >= 0) {
        lc += sp4(xB) * INV_NC;
        if (cB == (tcB >> 2)) lc -= comp4(xB, tcB & 3) * INV_NC;
    }

    // --- box path: 3 CIoUs SIMD-parallel on lanes 0..2 ---
    if (lane < MAXK && myBase >= 0) {
        float px  = sigf(br.x) * 2.f - 0.5f;
        float py  = sigf(br.y) * 2.f - 0.5f;
        float sw  = sigf(br.z) * 2.f;
        float shh = sigf(br.w) * 2.f;
        float pw  = sw * sw * an.x;
        float ph  = shh * shh * an.y;

        float ci = ciou(px, py, pw, ph, tb.x, tb.y, tb.z, tb.w);
        float v  = fmaxf(ci, 0.f);

        // epoch-tagged claim: stale runs never match tag -> no cleanup pass.
        unsigned pk  = (tag << 16) | (unsigned)__half_as_ushort(__float2half_rn(v));
        unsigned old = atomicExch(&g_tobj[SC<SI>::OFF + myBase], pk);
        float oldv = ((old >> 16) == tag)
                   ? __half2float(__ushort_as_half((unsigned short)(old & 0xFFFFu)))
                   : 0.f;

        lb += (1.f - ci) * INV_N;
        lo -= cn * (__half2float(__ushort_as_half((unsigned short)(pk & 0xFFFFu))) - oldv)
                 * SC<SI>::W;   // telescoping in half precision: sums to winner exactly
    }
}

// ---------------- fused kernel: dense loads prefetched over target phase ----
__global__ void __launch_bounds__(TPB, 4) k_all(P p, float* __restrict__ out) {
    __shared__ float    shp[24];
    __shared__ double   shd[24];
    __shared__ unsigned s_r;

    const int tid  = threadIdx.x;
    const int lane = tid & 31;
    const int wid  = tid >> 5;
    const int bx   = blockIdx.x;

    const unsigned tag = (g_epoch % 65535u) + 1u;   // 1..65535; never 0; differs from prev run

    // ==== dense prefetch: issue BOTH dense loads before the target phase ====
    // g1 < GSTR(151552) < Q0(153600) -> always inside cnf0 (unconditional load).
    const int g1 = bx * TPB + tid;
    const float4 dA = ((const float4*)p.cnf[0])[g1];

    // g2 spans the cnf0/cnf1/cnf2 boundary; guarded.
    const int g2 = g1 + GSTR;
    float4 dB = make_float4(0, 0, 0, 0);
    float  wB = 0.f;
    if (g2 < QTOT) {
        if (g2 < Q0)           { dB = ((const float4*)p.cnf[0])[g2];            wB = 4.0f / (float)M0; }
        else if (g2 < Q0 + Q1) { dB = ((const float4*)p.cnf[1])[g2 - Q0];       wB = 1.0f / (float)M1; }
        else                   { dB = ((const float4*)p.cnf[2])[g2 - Q0 - Q1];  wB = 0.4f / (float)M2; }
    }

    float lb = 0.f, lc = 0.f, lo = 0.f;

    // ---- target phase (overlaps with in-flight dense loads) ----
    if (bx < B1)        targets<0>(p, bx, tid, tag, lb, lc, lo);
    else if (bx < B2)   targets<1>(p, bx, tid, tag, lb, lc, lo);
    else if (bx < TBLK) targets<2>(p, bx, tid, tag, lb, lc, lo);

    // ---- dense softplus on prefetched registers ----
    lo += sp4(dA) * (4.0f / (float)M0);
    if (wB != 0.f) lo += sp4(dB) * wB;

    // ---- block reduce (3 floats) ----
    #pragma unroll
    for (int o = 16; o; o >>= 1) {
        lb += __shfl_down_sync(0xffffffffu, lb, o);
        lc += __shfl_down_sync(0xffffffffu, lc, o);
        lo += __shfl_down_sync(0xffffffffu, lo, o);
    }
    if (lane == 0) { shp[wid] = lb; shp[8 + wid] = lc; shp[16 + wid] = lo; }
    __syncthreads();

    // ---- publish partials + exit ticket (release; no L1-flush fence) ----
    if (tid == 0) {
        float a = 0.f, b = 0.f, c = 0.f;
        #pragma unroll
        for (int i = 0; i < 8; i++) { a += shp[i]; b += shp[8 + i]; c += shp[16 + i]; }
        g_pT[bx * 3 + 0] = a;
        g_pT[bx * 3 + 1] = b;
        g_pT[bx * 3 + 2] = c;
        s_r = ticket_acq_rel(&g_tk);
    }
    __syncthreads();

    // non-winners exit immediately; last block does the tiny final sum
    if (s_r == (unsigned)(NBLK - 1)) {
        double db = 0.0, dc = 0.0, dob = 0.0;
        for (int i = tid; i < NBLK; i += TPB) {
            db  += (double)__ldcg(&g_pT[i * 3 + 0]);
            dc  += (double)__ldcg(&g_pT[i * 3 + 1]);
            dob += (double)__ldcg(&g_pT[i * 3 + 2]);
        }
        #pragma unroll
        for (int o = 16; o; o >>= 1) {
            db  += __shfl_down_sync(0xffffffffu, db,  o);
            dc  += __shfl_down_sync(0xffffffffu, dc,  o);
            dob += __shfl_down_sync(0xffffffffu, dob, o);
        }
        if (lane == 0) { shd[wid] = db; shd[8 + wid] = dc; shd[16 + wid] = dob; }
        __syncthreads();
        if (tid == 0) {
            double b = 0.0, c = 0.0, o = 0.0;
            #pragma unroll
            for (int i = 0; i < 8; i++) { b += shd[i]; c += shd[8 + i]; o += shd[16 + i]; }
            out[0] = (float)(b * 1.6);    // lbox * 0.05 * 32
            out[1] = (float)(o * 22.4);   // lobj * 0.70 * 32
            out[2] = (float)(c * 9.6);    // lcls * 0.30 * 32
            g_epoch = g_epoch + 1u;       // next replay gets a fresh tag
            g_tk = 0u;                    // reset ticket
        }
    }
}

// ---------------- launch ----------------
extern "C" void kernel_launch(void* const* d_in, const int* in_sizes, int n_in,
                              void* d_out, int out_size) {
    // Disambiguate metadata ordering via in_sizes[3]:
    //  (A) reference-arg order -> in_sizes[3] == 24000 (tbox0)
    //  (B) setup_inputs insertion order per scale [box,cnf,cls,b,a,gy,gx,tcls,tbox,anc] -> 6000 (b0)
    P p;
    bool orderA = (n_in > 3 && in_sizes[3] == 24000);
    if (orderA) {
        for (int i = 0; i < 3; i++) {
            int f = 5 * i, g = 15 + 5 * i;
            p.box[i]  = (const float*)d_in[f + 0];
            p.cnf[i]  = (const float*)d_in[f + 1];
            p.cls[i]  = (const float*)d_in[f + 2];
            p.tbox[i] = (const float*)d_in[f + 3];
            p.anc[i]  = (const float*)d_in[f + 4];
            p.b[i]    = (const int*)d_in[g + 0];
            p.a[i]    = (const int*)d_in[g + 1];
            p.gy[i]   = (const int*)d_in[g + 2];
            p.gx[i]   = (const int*)d_in[g + 3];
            p.tc[i]   = (const int*)d_in[g + 4];
        }
    } else {
        for (int i = 0; i < 3; i++) {
            int q = 10 * i;
            p.box[i]  = (const float*)d_in[q + 0];
            p.cnf[i]  = (const float*)d_in[q + 1];
            p.cls[i]  = (const float*)d_in[q + 2];
            p.b[i]    = (const int*)d_in[q + 3];
            p.a[i]    = (const int*)d_in[q + 4];
            p.gy[i]   = (const int*)d_in[q + 5];
            p.gx[i]   = (const int*)d_in[q + 6];
            p.tc[i]   = (const int*)d_in[q + 7];
            p.tbox[i] = (const float*)d_in[q + 8];
            p.anc[i]  = (const float*)d_in[q + 9];
        }
    }

    k_all<<<NBLK, TPB>>>(p, (float*)d_out);
}

// round 14
// speedup vs baseline: 1.1496x; 1.1496x over previous
#include <cuda_runtime.h>
#include <cuda_fp16.h>
#include <math.h>

// ---------------- constants ----------------
#define NC 80
#define M0 614400
#define M1 153600
#define M2 38400

#define N0 6000
#define N1 4000
#define N2 2000

#define EPSV 1e-7f

#define TPB  256
#define NBLK 592              // one wave; no grid barrier -> no co-residency requirement
#define B1   250              // scale-0 target blocks [0,250)
#define B2   417              // scale-1 [250,417); scale-2 [417,501); dense-only [501,592)
#define TBLK 501
#define WS0  2000             // 250*8 warp slots (x3 lanes = 6000 targets)
#define WS1  1336             // 167*8 (x3 = 4008 >= 4000)
#define WS2  672              // 84*8  (x3 = 2016 >= 2000)
#define MAXK 3                // targets per warp, lanes 0..2 own one each

#define Q0 (M0/4)             // 153600 float4
#define Q1 (M1/4)             // 38400
#define Q2 (M2/4)             // 9600
#define QTOT (Q0+Q1+Q2)       // 201600
#define GSTR (NBLK*TPB)       // 151552 grid stride; GSTR < Q0, 2*GSTR > QTOT

// ---------------- scratch (no allocations allowed) ----------------
// g_tobj holds (tag<<16)|half(v). Stale entries invalidated by tag mismatch ->
// no cleanup pass needed between graph replays.
__device__ unsigned g_tobj[M0 + M1 + M2];   // zero at load (tag 0 never used)
__device__ float    g_pT[NBLK * 3];
__device__ unsigned g_epoch;                // bumped by ticket winner each run
__device__ unsigned g_tk;                   // exit ticket; winner resets

// ---------------- params ----------------
struct P {
    const float* box[3]; const float* cnf[3]; const float* cls[3];
    const float* tbox[3]; const float* anc[3];
    const int* b[3]; const int* a[3]; const int* gy[3]; const int* gx[3]; const int* tc[3];
};

// ---------------- helpers ----------------
__device__ __forceinline__ float sp(float x) {   // softplus = bce(x,0), fast
    return fmaxf(x, 0.f) + __logf(1.f + __expf(-fabsf(x)));
}
__device__ __forceinline__ float sp4(const float4& v) {
    return sp(v.x) + sp(v.y) + sp(v.z) + sp(v.w);
}
__device__ __forceinline__ float sigf(float x) {
    return __fdividef(1.f, 1.f + __expf(-x));
}
__device__ __forceinline__ float comp4(const float4& v, int c) {
    return (c & 2) ? ((c & 1) ? v.w : v.z) : ((c & 1) ? v.y : v.x);
}

__device__ __forceinline__ float ciou(float cx1, float cy1, float w1, float h1,
                                      float cx2, float cy2, float w2, float h2) {
    float x1a = cx1 - w1 * 0.5f, y1a = cy1 - h1 * 0.5f;
    float x2a = cx1 + w1 * 0.5f, y2a = cy1 + h1 * 0.5f;
    float x1b = cx2 - w2 * 0.5f, y1b = cy2 - h2 * 0.5f;
    float x2b = cx2 + w2 * 0.5f, y2b = cy2 + h2 * 0.5f;

    float iw = fmaxf(fminf(x2a, x2b) - fmaxf(x1a, x1b), 0.f);
    float ih = fmaxf(fminf(y2a, y2b) - fmaxf(y1a, y1b), 0.f);
    float inter = iw * ih;
    float uni = (x2a - x1a) * (y2a - y1a) + (x2b - x1b) * (y2b - y1b) - inter;
    float iou = __fdividef(inter, uni + EPSV);

    float cw = fmaxf(x2a, x2b) - fminf(x1a, x1b);
    float ch = fmaxf(y2a, y2b) - fminf(y1a, y1b);
    float diag = cw * cw + ch * ch + EPSV;
    float dx = (x1a + x2a) * 0.5f - (x1b + x2b) * 0.5f;
    float dy = (y1a + y2a) * 0.5f - (y1b + y2b) * 0.5f;
    float cent = dx * dx + dy * dy;

    float at = atanf(__fdividef(x2a - x1a, y2a - y1a + EPSV))
             - atanf(__fdividef(x2b - x1b, y2b - y1b + EPSV));
    const float C4PI2 = 4.0f / (float)(M_PI * M_PI);
    float v = C4PI2 * at * at;
    float alpha = __fdividef(v, v - iou + 1.f + EPSV);
    return iou - (__fdividef(cent, diag) + v * alpha);
}

// ---------------- per-scale compile-time constants ----------------
template<int SI> struct SC;
template<> struct SC<0> { static constexpr int DIM=80, OFF=0,     NTG=N0, WSL=WS0, BST=0;  static constexpr float W=4.0f/(float)M0; };
template<> struct SC<1> { static constexpr int DIM=40, OFF=M0,    NTG=N1, WSL=WS1, BST=B1; static constexpr float W=1.0f/(float)M1; };
template<> struct SC<2> { static constexpr int DIM=20, OFF=M0+M1, NTG=N2, WSL=WS2, BST=B2; static constexpr float W=0.4f/(float)M2; };

// ---------------- target phase: 3 targets/warp, lane-parallel ----------
template<int SI>
__device__ __forceinline__ void targets(const P& __restrict__ p, int bx, int tid,
                                        unsigned tag,
                                        float& lb, float& lc, float& lo) {
    const int lane = tid & 31;
    const int wid  = tid >> 5;
    constexpr int DIM = SC<SI>::DIM;
    constexpr float INV_N  = 1.f / (float)SC<SI>::NTG;
    constexpr float INV_NC = 1.f / ((float)SC<SI>::NTG * (float)NC);
    const unsigned FULL = 0xffffffffu;

    const int ws = (bx - SC<SI>::BST) * 8 + wid;

    // --- round 1: lanes 0..2 load their target's index tuple (parallel) ---
    int myBase = -1, myTc = 0, myT = 0;
    if (lane < MAXK) {
        int t = ws + lane * SC<SI>::WSL;
        if (t < SC<SI>::NTG) {
            int bb = p.b[SI][t], aa = p.a[SI][t];
            int yy = p.gy[SI][t], xx = p.gx[SI][t];
            myTc   = p.tc[SI][t];
            myT    = t;
            myBase = ((bb * 3 + aa) * DIM + yy) * DIM + xx;
        }
    }
    int base0 = __shfl_sync(FULL, myBase, 0);
    int base1 = __shfl_sync(FULL, myBase, 1);
    int base2 = __shfl_sync(FULL, myBase, 2);
    int tc0   = __shfl_sync(FULL, myTc, 0);
    int tc1   = __shfl_sync(FULL, myTc, 1);
    int tc2   = __shfl_sync(FULL, myTc, 2);

    // --- round 2: all independent gathers issue together ---
    float4 x0 = make_float4(0,0,0,0), x1 = x0, x2 = x0;
    if (lane < 20) {
        if (base0 >= 0) x0 = ((const float4*)p.cls[SI])[(size_t)base0 * (NC/4) + lane];
        if (base1 >= 0) x1 = ((const float4*)p.cls[SI])[(size_t)base1 * (NC/4) + lane];
        if (base2 >= 0) x2 = ((const float4*)p.cls[SI])[(size_t)base2 * (NC/4) + lane];
    }
    float4 br = make_float4(0,0,0,0), tb = br;
    float2 an = make_float2(0,0);
    float  cn = 0.f;
    if (lane < MAXK && myBase >= 0) {
        br = ((const float4*)p.box[SI])[myBase];
        an = ((const float2*)p.anc[SI])[myT];
        tb = ((const float4*)p.tbox[SI])[myT];
        cn = p.cnf[SI][myBase];
    }

    // --- cls: per-thread accumulation, no warp reduce ---
    if (lane < 20) {
        if (base0 >= 0) {
            lc += sp4(x0) * INV_NC;
            if (lane == (tc0 >> 2)) lc -= comp4(x0, tc0 & 3) * INV_NC;
        }
        if (base1 >= 0) {
            lc += sp4(x1) * INV_NC;
            if (lane == (tc1 >> 2)) lc -= comp4(x1, tc1 & 3) * INV_NC;
        }
        if (base2 >= 0) {
            lc += sp4(x2) * INV_NC;
            if (lane == (tc2 >> 2)) lc -= comp4(x2, tc2 & 3) * INV_NC;
        }
    }

    // --- box path: 3 CIoUs SIMD-parallel on lanes 0..2 ---
    if (lane < MAXK && myBase >= 0) {
        float px  = sigf(br.x) * 2.f - 0.5f;
        float py  = sigf(br.y) * 2.f - 0.5f;
        float sw  = sigf(br.z) * 2.f;
        float shh = sigf(br.w) * 2.f;
        float pw  = sw * sw * an.x;
        float ph  = shh * shh * an.y;

        float ci = ciou(px, py, pw, ph, tb.x, tb.y, tb.z, tb.w);
        float v  = fmaxf(ci, 0.f);

        // epoch-tagged claim: stale runs never match tag -> no cleanup pass.
        unsigned pk  = (tag << 16) | (unsigned)__half_as_ushort(__float2half_rn(v));
        unsigned old = atomicExch(&g_tobj[SC<SI>::OFF + myBase], pk);
        float oldv = ((old >> 16) == tag)
                   ? __half2float(__ushort_as_half((unsigned short)(old & 0xFFFFu)))
                   : 0.f;

        lb += (1.f - ci) * INV_N;
        lo -= cn * (__half2float(__ushort_as_half((unsigned short)(pk & 0xFFFFu))) - oldv)
                 * SC<SI>::W;   // telescoping in half precision: sums to winner exactly
    }
}

// ---------------- fused kernel: dense loads prefetched over target phase ----
__global__ void __launch_bounds__(TPB, 4) k_all(P p, float* __restrict__ out) {
    __shared__ float    shp[24];
    __shared__ double   shd[24];
    __shared__ unsigned s_r;

    const int tid  = threadIdx.x;
    const int lane = tid & 31;
    const int wid  = tid >> 5;
    const int bx   = blockIdx.x;

    const unsigned tag = (g_epoch % 65535u) + 1u;   // 1..65535; never 0; differs from prev run

    // ==== dense prefetch: issue BOTH dense loads before the target phase ====
    // g1 < GSTR(151552) < Q0(153600) -> always inside cnf0 (unconditional load).
    const int g1 = bx * TPB + tid;
    const float4 dA = ((const float4*)p.cnf[0])[g1];

    // g2 spans the cnf0/cnf1/cnf2 boundary; guarded.
    const int g2 = g1 + GSTR;
    float4 dB = make_float4(0, 0, 0, 0);
    float  wB = 0.f;
    if (g2 < QTOT) {
        if (g2 < Q0)           { dB = ((const float4*)p.cnf[0])[g2];            wB = 4.0f / (float)M0; }
        else if (g2 < Q0 + Q1) { dB = ((const float4*)p.cnf[1])[g2 - Q0];       wB = 1.0f / (float)M1; }
        else                   { dB = ((const float4*)p.cnf[2])[g2 - Q0 - Q1];  wB = 0.4f / (float)M2; }
    }

    float lb = 0.f, lc = 0.f, lo = 0.f;

    // ---- target phase (overlaps with in-flight dense loads) ----
    if (bx < B1)        targets<0>(p, bx, tid, tag, lb, lc, lo);
    else if (bx < B2)   targets<1>(p, bx, tid, tag, lb, lc, lo);
    else if (bx < TBLK) targets<2>(p, bx, tid, tag, lb, lc, lo);

    // ---- dense softplus on prefetched registers ----
    lo += sp4(dA) * (4.0f / (float)M0);
    if (wB != 0.f) lo += sp4(dB) * wB;

    // ---- block reduce (3 floats) ----
    #pragma unroll
    for (int o = 16; o; o >>= 1) {
        lb += __shfl_down_sync(0xffffffffu, lb, o);
        lc += __shfl_down_sync(0xffffffffu, lc, o);
        lo += __shfl_down_sync(0xffffffffu, lo, o);
    }
    if (lane == 0) { shp[wid] = lb; shp[8 + wid] = lc; shp[16 + wid] = lo; }
    __syncthreads();

    // ---- publish partials + exit ticket ----
    if (tid == 0) {
        float a = 0.f, b = 0.f, c = 0.f;
        #pragma unroll
        for (int i = 0; i < 8; i++) { a += shp[i]; b += shp[8 + i]; c += shp[16 + i]; }
        g_pT[bx * 3 + 0] = a;
        g_pT[bx * 3 + 1] = b;
        g_pT[bx * 3 + 2] = c;
        __threadfence();                  // stores visible before ticket
        s_r = atomicAdd(&g_tk, 1u);
    }
    __syncthreads();

    // non-winners exit immediately; last block does the tiny final sum
    if (s_r == (unsigned)(NBLK - 1)) {
        double db = 0.0, dc = 0.0, dob = 0.0;
        for (int i = tid; i < NBLK; i += TPB) {
            db  += (double)__ldcg(&g_pT[i * 3 + 0]);
            dc  += (double)__ldcg(&g_pT[i * 3 + 1]);
            dob += (double)__ldcg(&g_pT[i * 3 + 2]);
        }
        #pragma unroll
        for (int o = 16; o; o >>= 1) {
            db  += __shfl_down_sync(0xffffffffu, db,  o);
            dc  += __shfl_down_sync(0xffffffffu, dc,  o);
            dob += __shfl_down_sync(0xffffffffu, dob, o);
        }
        if (lane == 0) { shd[wid] = db; shd[8 + wid] = dc; shd[16 + wid] = dob; }
        __syncthreads();
        if (tid == 0) {
            double b = 0.0, c = 0.0, o = 0.0;
            #pragma unroll
            for (int i = 0; i < 8; i++) { b += shd[i]; c += shd[8 + i]; o += shd[16 + i]; }
            out[0] = (float)(b * 1.6);    // lbox * 0.05 * 32
            out[1] = (float)(o * 22.4);   // lobj * 0.70 * 32
            out[2] = (float)(c * 9.6);    // lcls * 0.30 * 32
            g_epoch = g_epoch + 1u;       // next replay gets a fresh tag
            g_tk = 0u;                    // reset ticket
        }
    }
}

// ---------------- launch ----------------
extern "C" void kernel_launch(void* const* d_in, const int* in_sizes, int n_in,
                              void* d_out, int out_size) {
    // Disambiguate metadata ordering via in_sizes[3]:
    //  (A) reference-arg order -> in_sizes[3] == 24000 (tbox0)
    //  (B) setup_inputs insertion order per scale [box,cnf,cls,b,a,gy,gx,tcls,tbox,anc] -> 6000 (b0)
    P p;
    bool orderA = (n_in > 3 && in_sizes[3] == 24000);
    if (orderA) {
        for (int i = 0; i < 3; i++) {
            int f = 5 * i, g = 15 + 5 * i;
            p.box[i]  = (const float*)d_in[f + 0];
            p.cnf[i]  = (const float*)d_in[f + 1];
            p.cls[i]  = (const float*)d_in[f + 2];
            p.tbox[i] = (const float*)d_in[f + 3];
            p.anc[i]  = (const float*)d_in[f + 4];
            p.b[i]    = (const int*)d_in[g + 0];
            p.a[i]    = (const int*)d_in[g + 1];
            p.gy[i]   = (const int*)d_in[g + 2];
            p.gx[i]   = (const int*)d_in[g + 3];
            p.tc[i]   = (const int*)d_in[g + 4];
        }
    } else {
        for (int i = 0; i < 3; i++) {
            int q = 10 * i;
            p.box[i]  = (const float*)d_in[q + 0];
            p.cnf[i]  = (const float*)d_in[q + 1];
            p.cls[i]  = (const float*)d_in[q + 2];
            p.b[i]    = (const int*)d_in[q + 3];
            p.a[i]    = (const int*)d_in[q + 4];
            p.gy[i]   = (const int*)d_in[q + 5];
            p.gx[i]   = (const int*)d_in[q + 6];
            p.tc[i]   = (const int*)d_in[q + 7];
            p.tbox[i] = (const float*)d_in[q + 8];
            p.anc[i]  = (const float*)d_in[q + 9];
        }
    }

    k_all<<<NBLK, TPB>>>(p, (float*)d_out);
}

// round 15
// speedup vs baseline: 1.1554x; 1.0050x over previous
#include <cuda_runtime.h>
#include <cuda_fp16.h>
#include <math.h>

// ---------------- constants ----------------
#define NC 80
#define M0 614400
#define M1 153600
#define M2 38400

#define N0 6000
#define N1 4000
#define N2 2000

#define EPSV 1e-7f

#define TPB  256
#define NBLK 592              // one wave; no grid barrier -> no co-residency requirement
#define B1   250              // scale-0 target blocks [0,250)
#define B2   417              // scale-1 [250,417); scale-2 [417,501); dense-only [501,592)
#define TBLK 501
#define WS0  2000             // 250*8 warp slots (x3 lanes = 6000 targets)
#define WS1  1336             // 167*8 (x3 = 4008 >= 4000)
#define WS2  672              // 84*8  (x3 = 2016 >= 2000)
#define MAXK 3                // targets per warp, lanes 0..2 own one each

#define Q0 (M0/4)             // 153600 float4
#define Q1 (M1/4)             // 38400
#define Q2 (M2/4)             // 9600
#define QTOT (Q0+Q1+Q2)       // 201600
#define GSTR (NBLK*TPB)       // 151552 grid stride; GSTR < Q0, 2*GSTR > QTOT

// ---------------- scratch (no allocations allowed) ----------------
// g_tobj holds (tag<<16)|half(v). Stale entries invalidated by tag mismatch ->
// no cleanup pass needed between graph replays.
__device__ unsigned g_tobj[M0 + M1 + M2];   // zero at load (tag 0 never used)
__device__ float    g_pT[NBLK * 3];
__device__ unsigned g_epoch;                // bumped by ticket winner each run
__device__ unsigned g_tk;                   // exit ticket; winner resets

// ---------------- params ----------------
struct P {
    const float* box[3]; const float* cnf[3]; const float* cls[3];
    const float* tbox[3]; const float* anc[3];
    const int* b[3]; const int* a[3]; const int* gy[3]; const int* gx[3]; const int* tc[3];
};

// ---------------- helpers ----------------
__device__ __forceinline__ float sp(float x) {   // softplus = bce(x,0), fast
    return fmaxf(x, 0.f) + __logf(1.f + __expf(-fabsf(x)));
}
__device__ __forceinline__ float sp4(const float4& v) {
    return sp(v.x) + sp(v.y) + sp(v.z) + sp(v.w);
}
__device__ __forceinline__ float sigf(float x) {
    return __fdividef(1.f, 1.f + __expf(-x));
}
__device__ __forceinline__ float comp4(const float4& v, int c) {
    return (c & 2) ? ((c & 1) ? v.w : v.z) : ((c & 1) ? v.y : v.x);
}

__device__ __forceinline__ float ciou(float cx1, float cy1, float w1, float h1,
                                      float cx2, float cy2, float w2, float h2) {
    float x1a = cx1 - w1 * 0.5f, y1a = cy1 - h1 * 0.5f;
    float x2a = cx1 + w1 * 0.5f, y2a = cy1 + h1 * 0.5f;
    float x1b = cx2 - w2 * 0.5f, y1b = cy2 - h2 * 0.5f;
    float x2b = cx2 + w2 * 0.5f, y2b = cy2 + h2 * 0.5f;

    float iw = fmaxf(fminf(x2a, x2b) - fmaxf(x1a, x1b), 0.f);
    float ih = fmaxf(fminf(y2a, y2b) - fmaxf(y1a, y1b), 0.f);
    float inter = iw * ih;
    float uni = (x2a - x1a) * (y2a - y1a) + (x2b - x1b) * (y2b - y1b) - inter;
    float iou = __fdividef(inter, uni + EPSV);

    float cw = fmaxf(x2a, x2b) - fminf(x1a, x1b);
    float ch = fmaxf(y2a, y2b) - fminf(y1a, y1b);
    float diag = cw * cw + ch * ch + EPSV;
    float dx = (x1a + x2a) * 0.5f - (x1b + x2b) * 0.5f;
    float dy = (y1a + y2a) * 0.5f - (y1b + y2b) * 0.5f;
    float cent = dx * dx + dy * dy;

    float at = atanf(__fdividef(x2a - x1a, y2a - y1a + EPSV))
             - atanf(__fdividef(x2b - x1b, y2b - y1b + EPSV));
    const float C4PI2 = 4.0f / (float)(M_PI * M_PI);
    float v = C4PI2 * at * at;
    float alpha = __fdividef(v, v - iou + 1.f + EPSV);
    return iou - (__fdividef(cent, diag) + v * alpha);
}

// release+acquire ticket: release orders this thread's prior global stores;
// the winner's acquire (same atomic) orders its subsequent loads. No CCTL.IVALL
// L1-flush, unlike __threadfence() (gpu-scope membar).
__device__ __forceinline__ unsigned ticket_acq_rel(unsigned* addr) {
    unsigned r;
    asm volatile("atom.acq_rel.gpu.global.add.u32 %0, [%1], %2;"
                 : "=r"(r) : "l"(addr), "r"(1u) : "memory");
    return r;
}

// ---------------- per-scale compile-time constants ----------------
template<int SI> struct SC;
template<> struct SC<0> { static constexpr int DIM=80, OFF=0,     NTG=N0, WSL=WS0, BST=0;  static constexpr float W=4.0f/(float)M0; };
template<> struct SC<1> { static constexpr int DIM=40, OFF=M0,    NTG=N1, WSL=WS1, BST=B1; static constexpr float W=1.0f/(float)M1; };
template<> struct SC<2> { static constexpr int DIM=20, OFF=M0+M1, NTG=N2, WSL=WS2, BST=B2; static constexpr float W=0.4f/(float)M2; };

// ---------------- target phase: 3 targets/warp, lane-parallel ----------
template<int SI>
__device__ __forceinline__ void targets(const P& __restrict__ p, int bx, int tid,
                                        unsigned tag,
                                        float& lb, float& lc, float& lo) {
    const int lane = tid & 31;
    const int wid  = tid >> 5;
    constexpr int DIM = SC<SI>::DIM;
    constexpr float INV_N  = 1.f / (float)SC<SI>::NTG;
    constexpr float INV_NC = 1.f / ((float)SC<SI>::NTG * (float)NC);
    const unsigned FULL = 0xffffffffu;

    const int ws = (bx - SC<SI>::BST) * 8 + wid;

    // --- round 1: lanes 0..2 load their target's index tuple (parallel) ---
    int myBase = -1, myTc = 0, myT = 0;
    if (lane < MAXK) {
        int t = ws + lane * SC<SI>::WSL;
        if (t < SC<SI>::NTG) {
            int bb = p.b[SI][t], aa = p.a[SI][t];
            int yy = p.gy[SI][t], xx = p.gx[SI][t];
            myTc   = p.tc[SI][t];
            myT    = t;
            myBase = ((bb * 3 + aa) * DIM + yy) * DIM + xx;
        }
    }
    int base0 = __shfl_sync(FULL, myBase, 0);
    int base1 = __shfl_sync(FULL, myBase, 1);
    int base2 = __shfl_sync(FULL, myBase, 2);
    int tc0   = __shfl_sync(FULL, myTc, 0);
    int tc1   = __shfl_sync(FULL, myTc, 1);
    int tc2   = __shfl_sync(FULL, myTc, 2);

    // --- round 2: all independent gathers issue together ---
    float4 x0 = make_float4(0,0,0,0), x1 = x0, x2 = x0;
    if (lane < 20) {
        if (base0 >= 0) x0 = ((const float4*)p.cls[SI])[(size_t)base0 * (NC/4) + lane];
        if (base1 >= 0) x1 = ((const float4*)p.cls[SI])[(size_t)base1 * (NC/4) + lane];
        if (base2 >= 0) x2 = ((const float4*)p.cls[SI])[(size_t)base2 * (NC/4) + lane];
    }
    float4 br = make_float4(0,0,0,0), tb = br;
    float2 an = make_float2(0,0);
    float  cn = 0.f;
    if (lane < MAXK && myBase >= 0) {
        br = ((const float4*)p.box[SI])[myBase];
        an = ((const float2*)p.anc[SI])[myT];
        tb = ((const float4*)p.tbox[SI])[myT];
        cn = p.cnf[SI][myBase];
    }

    // --- cls: per-thread accumulation, no warp reduce ---
    if (lane < 20) {
        if (base0 >= 0) {
            lc += sp4(x0) * INV_NC;
            if (lane == (tc0 >> 2)) lc -= comp4(x0, tc0 & 3) * INV_NC;
        }
        if (base1 >= 0) {
            lc += sp4(x1) * INV_NC;
            if (lane == (tc1 >> 2)) lc -= comp4(x1, tc1 & 3) * INV_NC;
        }
        if (base2 >= 0) {
            lc += sp4(x2) * INV_NC;
            if (lane == (tc2 >> 2)) lc -= comp4(x2, tc2 & 3) * INV_NC;
        }
    }

    // --- box path: 3 CIoUs SIMD-parallel on lanes 0..2 ---
    if (lane < MAXK && myBase >= 0) {
        float px  = sigf(br.x) * 2.f - 0.5f;
        float py  = sigf(br.y) * 2.f - 0.5f;
        float sw  = sigf(br.z) * 2.f;
        float shh = sigf(br.w) * 2.f;
        float pw  = sw * sw * an.x;
        float ph  = shh * shh * an.y;

        float ci = ciou(px, py, pw, ph, tb.x, tb.y, tb.z, tb.w);
        float v  = fmaxf(ci, 0.f);

        // epoch-tagged claim: stale runs never match tag -> no cleanup pass.
        unsigned pk  = (tag << 16) | (unsigned)__half_as_ushort(__float2half_rn(v));
        unsigned old = atomicExch(&g_tobj[SC<SI>::OFF + myBase], pk);
        float oldv = ((old >> 16) == tag)
                   ? __half2float(__ushort_as_half((unsigned short)(old & 0xFFFFu)))
                   : 0.f;

        lb += (1.f - ci) * INV_N;
        lo -= cn * (__half2float(__ushort_as_half((unsigned short)(pk & 0xFFFFu))) - oldv)
                 * SC<SI>::W;   // telescoping in half precision: sums to winner exactly
    }
}

// ---------------- fused kernel: dense loads prefetched over target phase ----
__global__ void __launch_bounds__(TPB, 4) k_all(P p, float* __restrict__ out) {
    __shared__ float    shp[24];
    __shared__ double   shd[24];
    __shared__ unsigned s_r;

    const int tid  = threadIdx.x;
    const int lane = tid & 31;
    const int wid  = tid >> 5;
    const int bx   = blockIdx.x;

    const unsigned tag = (g_epoch % 65535u) + 1u;   // 1..65535; never 0; differs from prev run

    // ==== dense prefetch: issue BOTH dense loads before the target phase ====
    // g1 < GSTR(151552) < Q0(153600) -> always inside cnf0 (unconditional load).
    const int g1 = bx * TPB + tid;
    const float4 dA = ((const float4*)p.cnf[0])[g1];

    // g2 spans the cnf0/cnf1/cnf2 boundary; guarded.
    const int g2 = g1 + GSTR;
    float4 dB = make_float4(0, 0, 0, 0);
    float  wB = 0.f;
    if (g2 < QTOT) {
        if (g2 < Q0)           { dB = ((const float4*)p.cnf[0])[g2];            wB = 4.0f / (float)M0; }
        else if (g2 < Q0 + Q1) { dB = ((const float4*)p.cnf[1])[g2 - Q0];       wB = 1.0f / (float)M1; }
        else                   { dB = ((const float4*)p.cnf[2])[g2 - Q0 - Q1];  wB = 0.4f / (float)M2; }
    }

    float lb = 0.f, lc = 0.f, lo = 0.f;

    // ---- target phase (overlaps with in-flight dense loads) ----
    if (bx < B1)        targets<0>(p, bx, tid, tag, lb, lc, lo);
    else if (bx < B2)   targets<1>(p, bx, tid, tag, lb, lc, lo);
    else if (bx < TBLK) targets<2>(p, bx, tid, tag, lb, lc, lo);

    // ---- dense softplus on prefetched registers ----
    lo += sp4(dA) * (4.0f / (float)M0);
    if (wB != 0.f) lo += sp4(dB) * wB;

    // ---- block reduce (3 floats) ----
    #pragma unroll
    for (int o = 16; o; o >>= 1) {
        lb += __shfl_down_sync(0xffffffffu, lb, o);
        lc += __shfl_down_sync(0xffffffffu, lc, o);
        lo += __shfl_down_sync(0xffffffffu, lo, o);
    }
    if (lane == 0) { shp[wid] = lb; shp[8 + wid] = lc; shp[16 + wid] = lo; }
    __syncthreads();

    // ---- publish partials + exit ticket (release; no L1-flush fence) ----
    if (tid == 0) {
        float a = 0.f, b = 0.f, c = 0.f;
        #pragma unroll
        for (int i = 0; i < 8; i++) { a += shp[i]; b += shp[8 + i]; c += shp[16 + i]; }
        g_pT[bx * 3 + 0] = a;
        g_pT[bx * 3 + 1] = b;
        g_pT[bx * 3 + 2] = c;
        s_r = ticket_acq_rel(&g_tk);
    }
    __syncthreads();

    // non-winners exit immediately; last block does the tiny final sum
    if (s_r == (unsigned)(NBLK - 1)) {
        double db = 0.0, dc = 0.0, dob = 0.0;
        for (int i = tid; i < NBLK; i += TPB) {
            db  += (double)__ldcg(&g_pT[i * 3 + 0]);
            dc  += (double)__ldcg(&g_pT[i * 3 + 1]);
            dob += (double)__ldcg(&g_pT[i * 3 + 2]);
        }
        #pragma unroll
        for (int o = 16; o; o >>= 1) {
            db  += __shfl_down_sync(0xffffffffu, db,  o);
            dc  += __shfl_down_sync(0xffffffffu, dc,  o);
            dob += __shfl_down_sync(0xffffffffu, dob, o);
        }
        if (lane == 0) { shd[wid] = db; shd[8 + wid] = dc; shd[16 + wid] = dob; }
        __syncthreads();
        if (tid == 0) {
            double b = 0.0, c = 0.0, o = 0.0;
            #pragma unroll
            for (int i = 0; i < 8; i++) { b += shd[i]; c += shd[8 + i]; o += shd[16 + i]; }
            out[0] = (float)(b * 1.6);    // lbox * 0.05 * 32
            out[1] = (float)(o * 22.4);   // lobj * 0.70 * 32
            out[2] = (float)(c * 9.6);    // lcls * 0.30 * 32
            g_epoch = g_epoch + 1u;       // next replay gets a fresh tag
            g_tk = 0u;                    // reset ticket
        }
    }
}

// ---------------- launch ----------------
extern "C" void kernel_launch(void* const* d_in, const int* in_sizes, int n_in,
                              void* d_out, int out_size) {
    // Disambiguate metadata ordering via in_sizes[3]:
    //  (A) reference-arg order -> in_sizes[3] == 24000 (tbox0)
    //  (B) setup_inputs insertion order per scale [box,cnf,cls,b,a,gy,gx,tcls,tbox,anc] -> 6000 (b0)
    P p;
    bool orderA = (n_in > 3 && in_sizes[3] == 24000);
    if (orderA) {
        for (int i = 0; i < 3; i++) {
            int f = 5 * i, g = 15 + 5 * i;
            p.box[i]  = (const float*)d_in[f + 0];
            p.cnf[i]  = (const float*)d_in[f + 1];
            p.cls[i]  = (const float*)d_in[f + 2];
            p.tbox[i] = (const float*)d_in[f + 3];
            p.anc[i]  = (const float*)d_in[f + 4];
            p.b[i]    = (const int*)d_in[g + 0];
            p.a[i]    = (const int*)d_in[g + 1];
            p.gy[i]   = (const int*)d_in[g + 2];
            p.gx[i]   = (const int*)d_in[g + 3];
            p.tc[i]   = (const int*)d_in[g + 4];
        }
    } else {
        for (int i = 0; i < 3; i++) {
            int q = 10 * i;
            p.box[i]  = (const float*)d_in[q + 0];
            p.cnf[i]  = (const float*)d_in[q + 1];
            p.cls[i]  = (const float*)d_in[q + 2];
            p.b[i]    = (const int*)d_in[q + 3];
            p.a[i]    = (const int*)d_in[q + 4];
            p.gy[i]   = (const int*)d_in[q + 5];
            p.gx[i]   = (const int*)d_in[q + 6];
            p.tc[i]   = (const int*)d_in[q + 7];
            p.tbox[i] = (const float*)d_in[q + 8];
            p.anc[i]  = (const float*)d_in[q + 9];
        }
    }

    k_all<<<NBLK, TPB>>>(p, (float*)d_out);
}